// round 1
// baseline (speedup 1.0000x reference)
#include <cuda_runtime.h>
#include <cstdint>

// ---------------------------------------------------------------------------
// Problem: out = gelu( x @ ((fc1_w^T @ fc2_w^T + b) * mask) )
//   x:    [B*D=49152, 1024]   fp32 row-major
//   fc1:  [4096, 1024]        (d, s) -> A of GEMM1 is column-major (k-major)
//   fc2:  [1024, 4096]        (t, d) -> B of GEMM1 is [N,K] row-major
//   bias: [1024], mask: [1024, 1024] (s, t)
// Two TF32 mma.sync GEMMs; attn staged in a __device__ scratch buffer.
// ---------------------------------------------------------------------------

__device__ float g_attn[1024 * 1024];  // GEMM1 output scratch (4 MB)

__device__ __forceinline__ uint32_t f2tf32(float f) {
    uint32_t r;
    asm("cvt.rna.tf32.f32 %0, %1;" : "=r"(r) : "f"(f));
    return r;
}

__device__ __forceinline__ void mma_tf32(float c[4], const uint32_t a[4], const uint32_t b[2]) {
    asm volatile(
        "mma.sync.aligned.m16n8k8.row.col.f32.tf32.tf32.f32 "
        "{%0,%1,%2,%3}, {%4,%5,%6,%7}, {%8,%9}, {%0,%1,%2,%3};"
        : "+f"(c[0]), "+f"(c[1]), "+f"(c[2]), "+f"(c[3])
        : "r"(a[0]), "r"(a[1]), "r"(a[2]), "r"(a[3]), "r"(b[0]), "r"(b[1]));
}

__device__ __forceinline__ float gelu_exact(float u) {
    return 0.5f * u * (1.0f + erff(u * 0.7071067811865476f));
}

// Tile config: block 128x128, K-step 16, 8 warps (2 n-warps x 4 m-warps),
// warp tile 32x64 -> 2 (m) x 8 (n) mma tiles of 16x8, 2 k-substeps.
constexpr int BM = 128, BN = 128, BK = 16;
constexpr int SKA = 20;   // A_s row stride (floats): bank = (20m+k)%32, conflict-free
constexpr int SNB = 136;  // B_s row stride: bank = (8k+n)%32, conflict-free

// AT: A stored globally as [K, M] (k-major / "transposed")  -- attn GEMM
// BT: B stored globally as [N, K] row-major                 -- attn GEMM
// EPI: 0 = (acc + bias[n]) * mask[m*N+n]; 1 = exact GELU
template <bool AT, bool BT, int EPI>
__global__ __launch_bounds__(256) void gemm_tf32(
    const float* __restrict__ A, const float* __restrict__ B, float* __restrict__ C,
    int M, int N, int K,
    const float* __restrict__ bias, const float* __restrict__ mask)
{
    __shared__ uint32_t As[BM * SKA];
    __shared__ uint32_t Bs[BK * SNB];

    const int tid  = threadIdx.x;
    const int lane = tid & 31;
    const int wid  = tid >> 5;
    const int wm   = (wid & 3) * 32;   // warp m-offset within block tile
    const int wn   = (wid >> 2) * 64;  // warp n-offset within block tile
    const int g    = lane >> 2;        // groupID
    const int tg   = lane & 3;         // threadID in group

    const int bm = blockIdx.y * BM;
    const int bn = blockIdx.x * BN;

    float c[2][8][4];
#pragma unroll
    for (int im = 0; im < 2; im++)
#pragma unroll
        for (int in = 0; in < 8; in++)
#pragma unroll
            for (int r = 0; r < 4; r++) c[im][in][r] = 0.0f;

    const int nk = K / BK;
    for (int kt = 0; kt < nk; kt++) {
        // ---- load A tile into As[m][k] (stride SKA) ----
#pragma unroll
        for (int l = 0; l < 2; l++) {
            int idx = tid + l * 256;  // 512 float4 loads
            if (!AT) {
                int m = idx >> 2, k4 = (idx & 3) << 2;
                float4 v = *reinterpret_cast<const float4*>(
                    A + (size_t)(bm + m) * K + kt * BK + k4);
                uint32_t* p = &As[m * SKA + k4];
                p[0] = f2tf32(v.x); p[1] = f2tf32(v.y);
                p[2] = f2tf32(v.z); p[3] = f2tf32(v.w);
            } else {
                int k = idx >> 5, m4 = (idx & 31) << 2;
                float4 v = *reinterpret_cast<const float4*>(
                    A + (size_t)(kt * BK + k) * M + bm + m4);
                As[(m4 + 0) * SKA + k] = f2tf32(v.x);
                As[(m4 + 1) * SKA + k] = f2tf32(v.y);
                As[(m4 + 2) * SKA + k] = f2tf32(v.z);
                As[(m4 + 3) * SKA + k] = f2tf32(v.w);
            }
        }
        // ---- load B tile into Bs[k][n] (stride SNB) ----
#pragma unroll
        for (int l = 0; l < 2; l++) {
            int idx = tid + l * 256;
            if (!BT) {
                int k = idx >> 5, n4 = (idx & 31) << 2;
                float4 v = *reinterpret_cast<const float4*>(
                    B + (size_t)(kt * BK + k) * N + bn + n4);
                uint32_t* p = &Bs[k * SNB + n4];
                p[0] = f2tf32(v.x); p[1] = f2tf32(v.y);
                p[2] = f2tf32(v.z); p[3] = f2tf32(v.w);
            } else {
                int n = idx >> 2, k4 = (idx & 3) << 2;
                float4 v = *reinterpret_cast<const float4*>(
                    B + (size_t)(bn + n) * K + kt * BK + k4);
                Bs[(k4 + 0) * SNB + n] = f2tf32(v.x);
                Bs[(k4 + 1) * SNB + n] = f2tf32(v.y);
                Bs[(k4 + 2) * SNB + n] = f2tf32(v.z);
                Bs[(k4 + 3) * SNB + n] = f2tf32(v.w);
            }
        }
        __syncthreads();

#pragma unroll
        for (int ks = 0; ks < BK; ks += 8) {
            uint32_t a[2][4];
#pragma unroll
            for (int im = 0; im < 2; im++) {
                int r = wm + im * 16 + g;
                a[im][0] = As[(r    ) * SKA + ks + tg    ];
                a[im][1] = As[(r + 8) * SKA + ks + tg    ];
                a[im][2] = As[(r    ) * SKA + ks + tg + 4];
                a[im][3] = As[(r + 8) * SKA + ks + tg + 4];
            }
            uint32_t b[8][2];
#pragma unroll
            for (int in = 0; in < 8; in++) {
                int col = wn + in * 8 + g;
                b[in][0] = Bs[(ks + tg    ) * SNB + col];
                b[in][1] = Bs[(ks + tg + 4) * SNB + col];
            }
#pragma unroll
            for (int im = 0; im < 2; im++)
#pragma unroll
                for (int in = 0; in < 8; in++)
                    mma_tf32(c[im][in], a[im], b[in]);
        }
        __syncthreads();
    }

    // ---- epilogue ----
#pragma unroll
    for (int im = 0; im < 2; im++) {
#pragma unroll
        for (int in = 0; in < 8; in++) {
            int r0 = bm + wm + im * 16 + g;
            int r1 = r0 + 8;
            int cc = bn + wn + in * 8 + tg * 2;
            float v0 = c[im][in][0], v1 = c[im][in][1];
            float v2 = c[im][in][2], v3 = c[im][in][3];
            if (EPI == 0) {
                float b0 = bias[cc], b1 = bias[cc + 1];
                v0 = (v0 + b0) * mask[(size_t)r0 * N + cc];
                v1 = (v1 + b1) * mask[(size_t)r0 * N + cc + 1];
                v2 = (v2 + b0) * mask[(size_t)r1 * N + cc];
                v3 = (v3 + b1) * mask[(size_t)r1 * N + cc + 1];
            } else {
                v0 = gelu_exact(v0); v1 = gelu_exact(v1);
                v2 = gelu_exact(v2); v3 = gelu_exact(v3);
            }
            *reinterpret_cast<float2*>(C + (size_t)r0 * N + cc) = make_float2(v0, v1);
            *reinterpret_cast<float2*>(C + (size_t)r1 * N + cc) = make_float2(v2, v3);
        }
    }
}

extern "C" void kernel_launch(void* const* d_in, const int* in_sizes, int n_in,
                              void* d_out, int out_size)
{
    const float* x    = (const float*)d_in[0];  // [49152, 1024]
    const float* fc1  = (const float*)d_in[1];  // [4096, 1024]
    const float* fc2  = (const float*)d_in[2];  // [1024, 4096]
    const float* bias = (const float*)d_in[3];  // [1024]
    const float* mask = (const float*)d_in[4];  // [1024, 1024]
    float* out = (float*)d_out;                 // [49152, 1024]

    float* attn;
    cudaGetSymbolAddress((void**)&attn, g_attn);

    // GEMM1: attn[s,t] = (sum_d fc1[d,s] * fc2[t,d] + bias[t]) * mask[s,t]
    // A = fc1 as [K=4096, M=1024] (k-major), B = fc2 as [N=1024, K=4096]
    gemm_tf32<true, true, 0><<<dim3(1024 / BN, 1024 / BM), 256>>>(
        fc1, fc2, attn, 1024, 1024, 4096, bias, mask);

    // GEMM2: out = gelu(x @ attn), M=49152, N=1024, K=1024
    gemm_tf32<false, false, 1><<<dim3(1024 / BN, 49152 / BM), 256>>>(
        x, attn, out, 49152, 1024, 1024, nullptr, nullptr);
}

// round 3
// speedup vs baseline: 1.8547x; 1.8547x over previous
#include <cuda_runtime.h>
#include <cstdint>

// ============================================================================
// out = gelu( x @ ((fc1_w^T @ fc2_w^T + b) * mask) )   — all fp32
//   x   [49152, 1024], fc1 [4096(d), 1024(s)], fc2 [1024(t), 4096(d)]
//   bias[1024], mask[1024(s), 1024(t)]
//
// compute_103 path (no tcgen05 on this toolchain target):
//   legacy mma.sync.m16n8k8 tf32 + ldmatrix fragments + 3-stage cp.async.
//   1. transpose fc1 -> fc1T [1024, 4096]
//   2. GEMM1 split-K=4: part[sk][s][t] = fc1T[s,:]·fc2[t,:] over k-range
//   3. fixup: attnT[t][s] = (sum_sk part + bias[t]) * mask[s][t]
//   4. GEMM2: out[m][t] = gelu( x[m,:]·attnT[t,:] )
// ============================================================================

__device__ float g_fc1T[1024 * 4096];
__device__ float g_part[4 * 1024 * 1024];
__device__ float g_attnT[1024 * 1024];

// ---------------- helpers ---------------------------------------------------
__device__ __forceinline__ uint32_t smem_u32(const void* p) {
    uint32_t a;
    asm("{ .reg .u64 t; cvta.to.shared.u64 t, %1; cvt.u32.u64 %0, t; }" : "=r"(a) : "l"(p));
    return a;
}
#define CP_ASYNC16(sdst, gsrc) \
    asm volatile("cp.async.cg.shared.global [%0], [%1], 16;" :: "r"(sdst), "l"(gsrc) : "memory")
#define CP_COMMIT() asm volatile("cp.async.commit_group;" ::: "memory")
#define CP_WAIT1()  asm volatile("cp.async.wait_group 1;" ::: "memory")
#define SWZ128(off) ((off) ^ (((off) >> 3) & 0x70))

__device__ __forceinline__ void ldsm_x4(uint32_t* r, uint32_t addr) {
    asm volatile("ldmatrix.sync.aligned.m8n8.x4.shared.b16 {%0,%1,%2,%3}, [%4];"
                 : "=r"(r[0]), "=r"(r[1]), "=r"(r[2]), "=r"(r[3]) : "r"(addr));
}
__device__ __forceinline__ uint32_t f2tf32u(uint32_t x) {
    uint32_t r;
    asm("cvt.rna.tf32.f32 %0, %1;" : "=r"(r) : "f"(__uint_as_float(x)));
    return r;
}
__device__ __forceinline__ void mma_tf32(float c[4], const uint32_t a[4], const uint32_t* b) {
    asm volatile(
        "mma.sync.aligned.m16n8k8.row.col.f32.tf32.tf32.f32 "
        "{%0,%1,%2,%3}, {%4,%5,%6,%7}, {%8,%9}, {%0,%1,%2,%3};"
        : "+f"(c[0]), "+f"(c[1]), "+f"(c[2]), "+f"(c[3])
        : "r"(a[0]), "r"(a[1]), "r"(a[2]), "r"(a[3]), "r"(b[0]), "r"(b[1]));
}
__device__ __forceinline__ float gelu_exact(float u) {
    return 0.5f * u * (1.0f + erff(u * 0.7071067811865476f));
}

// ---------------------------------------------------------------------------
// Tiled GEMM: per CTA 128(m) x 128(n), K chunks of 32 floats, 3-stage cp.async.
// A [*, lda] k-major, B [*, ldb] k-major, C = A·B^T (EPI=1: gelu; EPI=0: raw).
// blockIdx.z = split-K slice (offsets A,B by z*kSplit; C by z*M*N).
// ---------------------------------------------------------------------------
constexpr int STAGES = 3;
constexpr int ABYTES = 128 * 128;  // 128 rows x 32 f32 (128B, SW128)

template <int EPI>
__global__ __launch_bounds__(256, 2) void tc_gemm(
    const float* __restrict__ A, const float* __restrict__ B, float* __restrict__ C,
    int M, int N, int lda, int ldb, int kSplit)
{
    extern __shared__ __align__(1024) char smem[];
    const uint32_t sb = smem_u32(smem);
    const int tid  = threadIdx.x;
    const int lane = tid & 31;
    const int wid  = tid >> 5;
    const int wm   = (wid & 3) * 32;
    const int wn   = (wid >> 2) * 64;
    const size_t bm = (size_t)blockIdx.y * 128;
    const size_t bn = (size_t)blockIdx.x * 128;

    const float* Ab = A + (size_t)blockIdx.z * kSplit;
    const float* Bb = B + (size_t)blockIdx.z * kSplit;
    float* Cb = C + (size_t)blockIdx.z * ((size_t)M * N);

    const int nk = kSplit / 32;

    const int lr = tid >> 3;        // 0..31 (row group for cp.async)
    const int lc = tid & 7;         // 16B column
    auto issue = [&](int chunk) {
        const int buf = chunk % STAGES;
        const uint32_t aBase = sb + buf * ABYTES;
        const uint32_t bBase = sb + STAGES * ABYTES + buf * ABYTES;
        const float* ga = Ab + (bm + lr) * (size_t)lda + chunk * 32 + lc * 4;
        const float* gb = Bb + (bn + lr) * (size_t)ldb + chunk * 32 + lc * 4;
#pragma unroll
        for (int j = 0; j < 4; j++) {
            CP_ASYNC16(aBase + SWZ128((lr + j * 32) * 128 + lc * 16), ga + (size_t)(j * 32) * lda);
            CP_ASYNC16(bBase + SWZ128((lr + j * 32) * 128 + lc * 16), gb + (size_t)(j * 32) * ldb);
        }
        CP_COMMIT();
    };

    float c[2][8][4];
#pragma unroll
    for (int im = 0; im < 2; im++)
#pragma unroll
        for (int in = 0; in < 8; in++)
#pragma unroll
            for (int q = 0; q < 4; q++) c[im][in][q] = 0.0f;

    issue(0);
    issue(1);

    // ldmatrix lane addressing (b16 trick for tf32):
    // A frag (16m x 8k): row = wm + im*16 + (lane&15), 16B col = (lane>>4)&1
    // B pair (16n x 8k): row = wn + p*16 + (lane&7) + ((lane>>4)<<3), 16B col = (lane>>3)&1
    const int aRow = lane & 15;
    const int aKo  = ((lane >> 4) & 1) * 16;
    const int bRow = (lane & 7) + ((lane >> 4) << 3);
    const int bKo  = ((lane >> 3) & 1) * 16;

    for (int i = 0; i < nk; i++) {
        CP_WAIT1();
        __syncthreads();
        if (i + 2 < nk) issue(i + 2);

        const int buf = i % STAGES;
        const uint32_t aS = sb + buf * ABYTES;
        const uint32_t bS = sb + STAGES * ABYTES + buf * ABYTES;

#pragma unroll
        for (int ks = 0; ks < 4; ks++) {
            uint32_t af[2][4], bf[4][4];
#pragma unroll
            for (int im = 0; im < 2; im++)
                ldsm_x4(af[im], aS + SWZ128((wm + im * 16 + aRow) * 128 + ks * 32 + aKo));
#pragma unroll
            for (int p = 0; p < 4; p++)
                ldsm_x4(bf[p], bS + SWZ128((wn + p * 16 + bRow) * 128 + ks * 32 + bKo));
            // Unbiased tf32 rounding (raw truncation has ~1e-3 downward bias)
#pragma unroll
            for (int im = 0; im < 2; im++)
#pragma unroll
                for (int q = 0; q < 4; q++) af[im][q] = f2tf32u(af[im][q]);
#pragma unroll
            for (int p = 0; p < 4; p++)
#pragma unroll
                for (int q = 0; q < 4; q++) bf[p][q] = f2tf32u(bf[p][q]);

#pragma unroll
            for (int im = 0; im < 2; im++)
#pragma unroll
                for (int in = 0; in < 8; in++)
                    mma_tf32(c[im][in], af[im], &bf[in >> 1][(in & 1) * 2]);
        }
    }

    // ---------------- epilogue ----------------
    const int g  = lane >> 2;
    const int tg = lane & 3;
#pragma unroll
    for (int im = 0; im < 2; im++) {
#pragma unroll
        for (int in = 0; in < 8; in++) {
            const size_t r0 = bm + wm + im * 16 + g;
            const size_t r1 = r0 + 8;
            const size_t cc = bn + wn + in * 8 + tg * 2;
            float v0 = c[im][in][0], v1 = c[im][in][1];
            float v2 = c[im][in][2], v3 = c[im][in][3];
            if (EPI == 1) {
                v0 = gelu_exact(v0); v1 = gelu_exact(v1);
                v2 = gelu_exact(v2); v3 = gelu_exact(v3);
            }
            *reinterpret_cast<float2*>(Cb + r0 * N + cc) = make_float2(v0, v1);
            *reinterpret_cast<float2*>(Cb + r1 * N + cc) = make_float2(v2, v3);
        }
    }
}

// ---------------- fc1 transpose: [4096,1024] -> [1024,4096] -----------------
__global__ void transpose_k(const float* __restrict__ in, float* __restrict__ out,
                            int R, int Cc)
{
    __shared__ float t[32][33];
    int bx = blockIdx.x * 32;
    int by = blockIdx.y * 32;
    int x = threadIdx.x, y = threadIdx.y;
#pragma unroll
    for (int j = 0; j < 32; j += 8)
        t[y + j][x] = in[(size_t)(by + y + j) * Cc + bx + x];
    __syncthreads();
#pragma unroll
    for (int j = 0; j < 32; j += 8)
        out[(size_t)(bx + y + j) * R + by + x] = t[x][y + j];
}

// ---- fixup: attnT[t][s] = (sum_sk part[sk][s][t] + bias[t]) * mask[s][t] ----
__global__ void fixup_k(const float* __restrict__ part, const float* __restrict__ bias,
                        const float* __restrict__ mask, float* __restrict__ attnT)
{
    __shared__ float t[32][33];
    int bt = blockIdx.x * 32;   // t tile
    int bs = blockIdx.y * 32;   // s tile
    int x = threadIdx.x, y = threadIdx.y;
#pragma unroll
    for (int j = 0; j < 32; j += 8) {
        int s = bs + y + j, tc = bt + x;
        size_t idx = (size_t)s * 1024 + tc;
        float v = part[idx] + part[idx + 1048576] + part[idx + 2097152] + part[idx + 3145728];
        v = (v + bias[tc]) * mask[idx];
        t[y + j][x] = v;
    }
    __syncthreads();
#pragma unroll
    for (int j = 0; j < 32; j += 8)
        attnT[(size_t)(bt + y + j) * 1024 + bs + x] = t[x][y + j];
}

// ---------------------------------------------------------------------------
extern "C" void kernel_launch(void* const* d_in, const int* in_sizes, int n_in,
                              void* d_out, int out_size)
{
    const float* x    = (const float*)d_in[0];  // [49152, 1024]
    const float* fc1  = (const float*)d_in[1];  // [4096, 1024]
    const float* fc2  = (const float*)d_in[2];  // [1024, 4096]
    const float* bias = (const float*)d_in[3];  // [1024]
    const float* mask = (const float*)d_in[4];  // [1024, 1024]
    float* out = (float*)d_out;                 // [49152, 1024]

    float *fc1T, *part, *attnT;
    cudaGetSymbolAddress((void**)&fc1T, g_fc1T);
    cudaGetSymbolAddress((void**)&part, g_part);
    cudaGetSymbolAddress((void**)&attnT, g_attnT);

    constexpr int SMEM = 2 * STAGES * ABYTES;   // 98304
    cudaFuncSetAttribute(tc_gemm<0>, cudaFuncAttributeMaxDynamicSharedMemorySize, SMEM);
    cudaFuncSetAttribute(tc_gemm<1>, cudaFuncAttributeMaxDynamicSharedMemorySize, SMEM);

    // 1. fc1T[s][d] = fc1[d][s]
    transpose_k<<<dim3(32, 128), dim3(32, 8)>>>(fc1, fc1T, 4096, 1024);

    // 2. GEMM1 split-K=4: part[sk] = fc1T · fc2^T over k slice (raw)
    tc_gemm<0><<<dim3(8, 8, 4), 256, SMEM>>>(fc1T, fc2, part,
                                             1024, 1024, 4096, 4096, 1024);

    // 3. reduce + bias + mask + transpose -> attnT [t][s]
    fixup_k<<<dim3(32, 32), dim3(32, 8)>>>(part, bias, mask, attnT);

    // 4. GEMM2: out = gelu(x · attnT^T)
    tc_gemm<1><<<dim3(8, 384, 1), 256, SMEM>>>(x, attnT, out,
                                               49152, 1024, 1024, 1024, 1024);
}

// round 4
// speedup vs baseline: 2.0219x; 1.0902x over previous
#include <cuda_runtime.h>
#include <cstdint>

// ============================================================================
// out = gelu( x @ ((fc1_w^T @ fc2_w^T + b) * mask) )   — all fp32
//   x [49152,1024], fc1 [4096(d),1024(s)], fc2 [1024(t),4096(d)]
//   bias[1024], mask[1024(s),1024(t)]
//
// Legacy mma.sync tf32 path (compute_103 target: no tcgen05).
// All operands PRE-ROUNDED to tf32 (cvt.rna) outside the GEMM mainloop:
//   round(x)->g_xr, round(fc2)->g_fc2r, transpose+round(fc1)->g_fc1T,
//   fixup rounds attnT. Mainloop = LDSM + HMMA only.
// ============================================================================

__device__ float g_xr[49152 * 1024];
__device__ float g_fc1T[1024 * 4096];
__device__ float g_fc2r[1024 * 4096];
__device__ float g_part[4 * 1024 * 1024];
__device__ float g_attnT[1024 * 1024];

// ---------------- helpers ---------------------------------------------------
__device__ __forceinline__ uint32_t smem_u32(const void* p) {
    uint32_t a;
    asm("{ .reg .u64 t; cvta.to.shared.u64 t, %1; cvt.u32.u64 %0, t; }" : "=r"(a) : "l"(p));
    return a;
}
#define CP_ASYNC16(sdst, gsrc) \
    asm volatile("cp.async.cg.shared.global [%0], [%1], 16;" :: "r"(sdst), "l"(gsrc) : "memory")
#define CP_COMMIT() asm volatile("cp.async.commit_group;" ::: "memory")
#define CP_WAIT1()  asm volatile("cp.async.wait_group 1;" ::: "memory")
#define SWZ128(off) ((off) ^ (((off) >> 3) & 0x70))

__device__ __forceinline__ void ldsm_x4(uint32_t* r, uint32_t addr) {
    asm volatile("ldmatrix.sync.aligned.m8n8.x4.shared.b16 {%0,%1,%2,%3}, [%4];"
                 : "=r"(r[0]), "=r"(r[1]), "=r"(r[2]), "=r"(r[3]) : "r"(addr));
}
__device__ __forceinline__ float f2tf32f(float x) {
    uint32_t r;
    asm("cvt.rna.tf32.f32 %0, %1;" : "=r"(r) : "f"(x));
    return __uint_as_float(r);
}
__device__ __forceinline__ void mma_tf32(float c[4], const uint32_t a[4], const uint32_t* b) {
    asm volatile(
        "mma.sync.aligned.m16n8k8.row.col.f32.tf32.tf32.f32 "
        "{%0,%1,%2,%3}, {%4,%5,%6,%7}, {%8,%9}, {%0,%1,%2,%3};"
        : "+f"(c[0]), "+f"(c[1]), "+f"(c[2]), "+f"(c[3])
        : "r"(a[0]), "r"(a[1]), "r"(a[2]), "r"(a[3]), "r"(b[0]), "r"(b[1]));
}
__device__ __forceinline__ float gelu_exact(float u) {
    return 0.5f * u * (1.0f + erff(u * 0.7071067811865476f));
}

// ---------------------------------------------------------------------------
// Tiled GEMM: per CTA 128(m) x 128(n), K chunks of 32 floats, 3-stage cp.async.
// Operands assumed pre-rounded to tf32. A [*,lda], B [*,ldb] k-major, C=A·B^T.
// EPI=1: gelu store; EPI=0: raw store. blockIdx.z = split-K slice.
// ---------------------------------------------------------------------------
constexpr int STAGES = 3;
constexpr int ABYTES = 128 * 128;

template <int EPI>
__global__ __launch_bounds__(256, 2) void tc_gemm(
    const float* __restrict__ A, const float* __restrict__ B, float* __restrict__ C,
    int M, int N, int lda, int ldb, int kSplit)
{
    extern __shared__ __align__(1024) char smem[];
    const uint32_t sb = smem_u32(smem);
    const int tid  = threadIdx.x;
    const int lane = tid & 31;
    const int wid  = tid >> 5;
    const int wm   = (wid & 3) * 32;
    const int wn   = (wid >> 2) * 64;
    const size_t bm = (size_t)blockIdx.y * 128;
    const size_t bn = (size_t)blockIdx.x * 128;

    const float* Ab = A + (size_t)blockIdx.z * kSplit;
    const float* Bb = B + (size_t)blockIdx.z * kSplit;
    float* Cb = C + (size_t)blockIdx.z * ((size_t)M * N);

    const int nk = kSplit / 32;

    const int lr = tid >> 3;
    const int lc = tid & 7;
    auto issue = [&](int chunk) {
        const int buf = chunk % STAGES;
        const uint32_t aBase = sb + buf * ABYTES;
        const uint32_t bBase = sb + STAGES * ABYTES + buf * ABYTES;
        const float* ga = Ab + (bm + lr) * (size_t)lda + chunk * 32 + lc * 4;
        const float* gb = Bb + (bn + lr) * (size_t)ldb + chunk * 32 + lc * 4;
#pragma unroll
        for (int j = 0; j < 4; j++) {
            CP_ASYNC16(aBase + SWZ128((lr + j * 32) * 128 + lc * 16), ga + (size_t)(j * 32) * lda);
            CP_ASYNC16(bBase + SWZ128((lr + j * 32) * 128 + lc * 16), gb + (size_t)(j * 32) * ldb);
        }
        CP_COMMIT();
    };

    float c[2][8][4];
#pragma unroll
    for (int im = 0; im < 2; im++)
#pragma unroll
        for (int in = 0; in < 8; in++)
#pragma unroll
            for (int q = 0; q < 4; q++) c[im][in][q] = 0.0f;

    issue(0);
    issue(1);

    const int aRow = lane & 15;
    const int aKo  = ((lane >> 4) & 1) * 16;
    const int bRow = (lane & 7) + ((lane >> 4) << 3);
    const int bKo  = ((lane >> 3) & 1) * 16;

    for (int i = 0; i < nk; i++) {
        CP_WAIT1();
        __syncthreads();
        if (i + 2 < nk) issue(i + 2);

        const int buf = i % STAGES;
        const uint32_t aS = sb + buf * ABYTES;
        const uint32_t bS = sb + STAGES * ABYTES + buf * ABYTES;

#pragma unroll
        for (int ks = 0; ks < 4; ks++) {
            uint32_t af[2][4], bf[4][4];
#pragma unroll
            for (int im = 0; im < 2; im++)
                ldsm_x4(af[im], aS + SWZ128((wm + im * 16 + aRow) * 128 + ks * 32 + aKo));
#pragma unroll
            for (int p = 0; p < 4; p++)
                ldsm_x4(bf[p], bS + SWZ128((wn + p * 16 + bRow) * 128 + ks * 32 + bKo));
#pragma unroll
            for (int im = 0; im < 2; im++)
#pragma unroll
                for (int in = 0; in < 8; in++)
                    mma_tf32(c[im][in], af[im], &bf[in >> 1][(in & 1) * 2]);
        }
    }

    // ---------------- epilogue ----------------
    const int g  = lane >> 2;
    const int tg = lane & 3;
#pragma unroll
    for (int im = 0; im < 2; im++) {
#pragma unroll
        for (int in = 0; in < 8; in++) {
            const size_t r0 = bm + wm + im * 16 + g;
            const size_t r1 = r0 + 8;
            const size_t cc = bn + wn + in * 8 + tg * 2;
            float v0 = c[im][in][0], v1 = c[im][in][1];
            float v2 = c[im][in][2], v3 = c[im][in][3];
            if (EPI == 1) {
                v0 = gelu_exact(v0); v1 = gelu_exact(v1);
                v2 = gelu_exact(v2); v3 = gelu_exact(v3);
            }
            *reinterpret_cast<float2*>(Cb + r0 * N + cc) = make_float2(v0, v1);
            *reinterpret_cast<float2*>(Cb + r1 * N + cc) = make_float2(v2, v3);
        }
    }
}

// --------------- tf32 pre-round pass: out[i] = rna_tf32(in[i]) --------------
__global__ __launch_bounds__(256) void round_pass(const float4* __restrict__ in,
                                                  float4* __restrict__ out, int n4)
{
    int i = blockIdx.x * 256 + threadIdx.x;
    int stride = gridDim.x * 256;
    for (; i < n4; i += stride) {
        float4 v = in[i];
        v.x = f2tf32f(v.x); v.y = f2tf32f(v.y);
        v.z = f2tf32f(v.z); v.w = f2tf32f(v.w);
        out[i] = v;
    }
}

// ------- fc1 transpose + round: [4096,1024] -> [1024,4096] (tf32) -----------
__global__ void transpose_k(const float* __restrict__ in, float* __restrict__ out,
                            int R, int Cc)
{
    __shared__ float t[32][33];
    int bx = blockIdx.x * 32;
    int by = blockIdx.y * 32;
    int x = threadIdx.x, y = threadIdx.y;
#pragma unroll
    for (int j = 0; j < 32; j += 8)
        t[y + j][x] = f2tf32f(in[(size_t)(by + y + j) * Cc + bx + x]);
    __syncthreads();
#pragma unroll
    for (int j = 0; j < 32; j += 8)
        out[(size_t)(bx + y + j) * R + by + x] = t[x][y + j];
}

// fixup: attnT[t][s] = rna_tf32( (sum_sk part[sk][s][t] + bias[t]) * mask[s][t] )
__global__ void fixup_k(const float* __restrict__ part, const float* __restrict__ bias,
                        const float* __restrict__ mask, float* __restrict__ attnT)
{
    __shared__ float t[32][33];
    int bt = blockIdx.x * 32;
    int bs = blockIdx.y * 32;
    int x = threadIdx.x, y = threadIdx.y;
#pragma unroll
    for (int j = 0; j < 32; j += 8) {
        int s = bs + y + j, tc = bt + x;
        size_t idx = (size_t)s * 1024 + tc;
        float v = part[idx] + part[idx + 1048576] + part[idx + 2097152] + part[idx + 3145728];
        v = (v + bias[tc]) * mask[idx];
        t[y + j][x] = f2tf32f(v);
    }
    __syncthreads();
#pragma unroll
    for (int j = 0; j < 32; j += 8)
        attnT[(size_t)(bt + y + j) * 1024 + bs + x] = t[x][y + j];
}

// ---------------------------------------------------------------------------
extern "C" void kernel_launch(void* const* d_in, const int* in_sizes, int n_in,
                              void* d_out, int out_size)
{
    const float* x    = (const float*)d_in[0];
    const float* fc1  = (const float*)d_in[1];
    const float* fc2  = (const float*)d_in[2];
    const float* bias = (const float*)d_in[3];
    const float* mask = (const float*)d_in[4];
    float* out = (float*)d_out;

    float *xr, *fc1T, *fc2r, *part, *attnT;
    cudaGetSymbolAddress((void**)&xr, g_xr);
    cudaGetSymbolAddress((void**)&fc1T, g_fc1T);
    cudaGetSymbolAddress((void**)&fc2r, g_fc2r);
    cudaGetSymbolAddress((void**)&part, g_part);
    cudaGetSymbolAddress((void**)&attnT, g_attnT);

    constexpr int SMEM = 2 * STAGES * ABYTES;   // 98304
    cudaFuncSetAttribute(tc_gemm<0>, cudaFuncAttributeMaxDynamicSharedMemorySize, SMEM);
    cudaFuncSetAttribute(tc_gemm<1>, cudaFuncAttributeMaxDynamicSharedMemorySize, SMEM);

    // Pre-round operands to tf32 (unbiased RNA) so GEMM mainloops have no cvt.
    round_pass<<<1184, 256>>>((const float4*)x, (float4*)xr, 49152 * 1024 / 4);
    round_pass<<<1184, 256>>>((const float4*)fc2, (float4*)fc2r, 1024 * 4096 / 4);

    // fc1T[s][d] = round(fc1[d][s])
    transpose_k<<<dim3(32, 128), dim3(32, 8)>>>(fc1, fc1T, 4096, 1024);

    // GEMM1 split-K=4: part[sk] = fc1T · fc2r^T over k slice
    tc_gemm<0><<<dim3(8, 8, 4), 256, SMEM>>>(fc1T, fc2r, part,
                                             1024, 1024, 4096, 4096, 1024);

    // reduce + bias + mask + transpose + round -> attnT [t][s]
    fixup_k<<<dim3(32, 32), dim3(32, 8)>>>(part, bias, mask, attnT);

    // GEMM2: out = gelu(xr · attnT^T)
    tc_gemm<1><<<dim3(8, 384, 1), 256, SMEM>>>(xr, attnT, out,
                                               49152, 1024, 1024, 1024, 1024);
}